// round 8
// baseline (speedup 1.0000x reference)
#include <cuda_runtime.h>
#include <cuda_bf16.h>
#include <math.h>

#define BATCH 16384
#define DIM   2048
#define NC    250
#define NCP   256
#define F_MARGIN 1.2f
#define F_TOPO_TH 0.3f
#define F_EPS 1e-12f

// ---------------- scratch (static device memory; no allocs) ----------------
__device__ __align__(16) float          g_sums[NC * DIM];     // per-class sums
__device__ __align__(16) float          g_cent[NC * DIM];     // fp32 centroids
__device__ __align__(16) __nv_bfloat16  g_cbf[NCP * DIM];     // normalized centroids bf16 (padded)
__device__ float        g_cn2[NCP];                           // |c_hat_bf16|^2
__device__ float        g_c2[NC];                             // |centroid|^2 fp32
__device__ int          g_counts[NCP];
__device__ float        g_pair[NC * NCP];                     // hinge segment sums
__device__ float        g_pdist[NC * NC];
__device__ float        g_ce;
__device__ unsigned int g_pmax;
__device__ unsigned int g_mmax;

// ---------------- init: zero accumulators ----------------
__global__ void k_init() {
    int i = blockIdx.x * blockDim.x + threadIdx.x;
    for (int k = i; k < NC * NCP; k += gridDim.x * blockDim.x) g_pair[k] = 0.f;
    if (i < NCP) g_counts[i] = 0;
    if (i == 0) { g_ce = 0.f; g_pmax = 0u; g_mmax = 0u; }
}

// ---------------- cross-entropy (1 warp / row) + label counts ----------------
__global__ void k_ce(const float* __restrict__ logits, const int* __restrict__ labels) {
    __shared__ float bsum;
    if (threadIdx.x == 0) bsum = 0.f;
    __syncthreads();
    int w = threadIdx.x >> 5, lane = threadIdx.x & 31;
    int row = blockIdx.x * 8 + w;
    const float* lr = logits + (size_t)row * NC;
    float x[8], m = -1e30f;
#pragma unroll
    for (int i = 0; i < 8; i++) {
        int c = lane + 32 * i;
        x[i] = (c < NC) ? lr[c] : -1e30f;
        m = fmaxf(m, x[i]);
    }
    for (int o = 16; o; o >>= 1) m = fmaxf(m, __shfl_xor_sync(0xffffffffu, m, o));
    float s = 0.f;
#pragma unroll
    for (int i = 0; i < 8; i++) { int c = lane + 32 * i; if (c < NC) s += expf(x[i] - m); }
    for (int o = 16; o; o >>= 1) s += __shfl_xor_sync(0xffffffffu, s, o);
    if (lane == 0) {
        int lab = labels[row];
        float lp = (lr[lab] - m) - logf(s);
        atomicAdd(&bsum, -lp);
        atomicAdd(&g_counts[lab], 1);
    }
    __syncthreads();
    if (threadIdx.x == 0) atomicAdd(&g_ce, bsum);
}

// ---------------- max of topo matrix ----------------
__global__ void k_mmax(const float* __restrict__ M) {
    float m = 0.f;
    for (int i = blockIdx.x * blockDim.x + threadIdx.x; i < NC * NC; i += gridDim.x * blockDim.x)
        m = fmaxf(m, M[i]);
    for (int o = 16; o; o >>= 1) m = fmaxf(m, __shfl_xor_sync(0xffffffffu, m, o));
    __shared__ float wm[8];
    if ((threadIdx.x & 31) == 0) wm[threadIdx.x >> 5] = m;
    __syncthreads();
    if (threadIdx.x == 0) {
        float r = 0.f;
#pragma unroll
        for (int i = 0; i < 8; i++) r = fmaxf(r, wm[i]);
        atomicMax(&g_mmax, __float_as_uint(r));
    }
}

// ---------------- segment sum: per-warp private accumulators (no atomics) ----------------
// grid = DIM/16 blocks; block bx owns 16-column stripe; warp w owns rows [w*2048, w*2048+2048)
__global__ void k_segsum(const float* __restrict__ emb, const int* __restrict__ labels) {
    extern __shared__ float acc[]; // 8 * NC * 16 floats
    int t = threadIdx.x, w = t >> 5, lane = t & 31;
    float* accw = acc + w * (NC * 16);
    for (int i = t; i < 8 * NC * 16; i += 256) acc[i] = 0.f;
    __syncthreads();
    int s0 = blockIdx.x * 16;
    int col = lane & 15;
    int hi = lane >> 4;
    int rbase = w * 2048;
    for (int it = 0; it < 2048; it += 16) {
        float v[8]; int lb[8];
#pragma unroll
        for (int j = 0; j < 8; j++) {
            int r = rbase + it + 2 * j + hi;
            v[j]  = emb[(size_t)r * DIM + s0 + col];
            lb[j] = labels[r];
        }
#pragma unroll
        for (int j = 0; j < 8; j++) {
            if (hi == 0) accw[lb[j] * 16 + col] += v[j];
            __syncwarp();
            if (hi == 1) accw[lb[j] * 16 + col] += v[j];
            __syncwarp();
        }
    }
    __syncthreads();
    for (int i = t; i < NC * 16; i += 256) {
        float s = 0.f;
#pragma unroll
        for (int w2 = 0; w2 < 8; w2++) s += acc[w2 * NC * 16 + i];
        int c = i >> 4, cc = i & 15;
        g_sums[c * DIM + s0 + cc] = s;
    }
}

// ---------------- centroid finalize: fp32 centroids + normalized bf16 copy ----------------
__global__ void k_centfin() {
    int c = blockIdx.x, t = threadIdx.x;
    __shared__ float cache[DIM];
    __shared__ float red[8];
    if (c >= NC) {
        for (int d = t; d < DIM; d += 256) g_cbf[(size_t)c * DIM + d] = __float2bfloat16(0.f);
        if (t == 0) g_cn2[c] = 0.f;
        return;
    }
    float denom = 1.f / fmaxf((float)g_counts[c], 1.f);
    float s2 = 0.f;
    for (int d = t; d < DIM; d += 256) {
        float v = g_sums[c * DIM + d] * denom;
        cache[d] = v;
        g_cent[c * DIM + d] = v;
        s2 += v * v;
    }
    for (int o = 16; o; o >>= 1) s2 += __shfl_xor_sync(0xffffffffu, s2, o);
    if ((t & 31) == 0) red[t >> 5] = s2;
    __syncthreads();
    float tot = 0.f;
#pragma unroll
    for (int i = 0; i < 8; i++) tot += red[i];
    float inv = 1.f / fmaxf(sqrtf(tot), F_EPS);
    float q2 = 0.f;
    for (int d = t; d < DIM; d += 256) {
        __nv_bfloat16 b = __float2bfloat16(cache[d] * inv);
        g_cbf[(size_t)c * DIM + d] = b;
        float f = __bfloat162float(b);
        q2 += f * f;
    }
    for (int o = 16; o; o >>= 1) q2 += __shfl_xor_sync(0xffffffffu, q2, o);
    __syncthreads();
    if ((t & 31) == 0) red[t >> 5] = q2;
    __syncthreads();
    if (t == 0) {
        float tq = 0.f;
#pragma unroll
        for (int i = 0; i < 8; i++) tq += red[i];
        g_cn2[c] = tq;
        g_c2[c]  = tot;
    }
}

// ---------------- centroid pairwise distance (fp32 exact) + pmax ----------------
__global__ void k_pdist() {
    __shared__ float ri[DIM];
    __shared__ float wm[8];
    int i = blockIdx.x, t = threadIdx.x;
    for (int d = t; d < DIM; d += 256) ri[d] = g_cent[i * DIM + d];
    __syncthreads();
    float pm = 0.f;
    if (t < NC) {
        int j = t;
        const float* rj = g_cent + (size_t)j * DIM;
        float d0 = 0.f, d1 = 0.f, d2 = 0.f, d3 = 0.f;
#pragma unroll 4
        for (int d = 0; d < DIM; d += 4) {
            float4 v = *(const float4*)(rj + d);
            d0 += ri[d] * v.x; d1 += ri[d + 1] * v.y;
            d2 += ri[d + 2] * v.z; d3 += ri[d + 3] * v.w;
        }
        float dot = (d0 + d1) + (d2 + d3);
        float pd = sqrtf(fmaxf(g_c2[i] + g_c2[j] - 2.f * dot, 0.f) + F_EPS);
        g_pdist[i * NC + j] = pd;
        if (g_counts[i] > 0 && g_counts[j] > 0) pm = pd;
    }
    for (int o = 16; o; o >>= 1) pm = fmaxf(pm, __shfl_xor_sync(0xffffffffu, pm, o));
    if ((t & 31) == 0) wm[t >> 5] = pm;
    __syncthreads();
    if (t == 0) {
        float r = 0.f;
#pragma unroll
        for (int k = 0; k < 8; k++) r = fmaxf(r, wm[k]);
        atomicMax(&g_pmax, __float_as_uint(r));
    }
}

// ---------------- margin GEMM: emb(bf16) x centn(bf16)^T with fp32 accum ----------------
// block tile 128(m) x 128(n), k-chunk 32; 8 warps as 4x2 -> warp tile 32x64
__global__ __launch_bounds__(256, 1) void k_margin(const float* __restrict__ emb,
                                                   const int* __restrict__ labels) {
    __shared__ __align__(16) __nv_bfloat16 At[128][40];
    __shared__ __align__(16) __nv_bfloat16 Bt[128][40];
    __shared__ int   lab[128];
    __shared__ float rs[256];
    __shared__ float invn[128];
    int t = threadIdx.x;
    int by = blockIdx.x, ny = blockIdx.y;
    if (t < 128) lab[t] = labels[by * 128 + t];
    int lrow = t >> 1, lhalf = t & 1;
    const float* arow = emb + (size_t)(by * 128 + lrow) * DIM + lhalf * 16;
    const __nv_bfloat16* brow = g_cbf + (size_t)(ny * 128 + lrow) * DIM + lhalf * 16;
    float sq = 0.f;
    int wid = t >> 5, lane = t & 31;
    int wm = (wid & 3) * 32, wn = (wid >> 2) * 64;
    int sub = lane >> 3, rr = lane & 7;
    float acc[2][8][4];
#pragma unroll
    for (int a = 0; a < 2; a++)
#pragma unroll
        for (int b = 0; b < 8; b++)
#pragma unroll
            for (int c = 0; c < 4; c++) acc[a][b][c] = 0.f;

    for (int kc = 0; kc < DIM; kc += 32) {
        // A: fp32 global -> bf16 smem (+ row sumsq on the side)
#pragma unroll
        for (int q = 0; q < 4; q++) {
            float4 v = *(const float4*)(arow + kc + q * 4);
            sq += v.x * v.x + v.y * v.y + v.z * v.z + v.w * v.w;
            __nv_bfloat162* dst = (__nv_bfloat162*)&At[lrow][lhalf * 16 + q * 4];
            __nv_bfloat162 p0, p1;
            p0.x = __float2bfloat16(v.x); p0.y = __float2bfloat16(v.y);
            p1.x = __float2bfloat16(v.z); p1.y = __float2bfloat16(v.w);
            dst[0] = p0; dst[1] = p1;
        }
        // B: bf16 global -> smem
#pragma unroll
        for (int q = 0; q < 2; q++) {
            uint4 u = *(const uint4*)(brow + kc + q * 8);
            *(uint4*)&Bt[lrow][lhalf * 16 + q * 8] = u;
        }
        __syncthreads();
#pragma unroll
        for (int ks = 0; ks < 32; ks += 16) {
            unsigned a[2][4];
#pragma unroll
            for (int mf = 0; mf < 2; mf++) {
                unsigned ad = (unsigned)__cvta_generic_to_shared(
                    &At[wm + mf * 16 + (sub & 1) * 8 + rr][ks + (sub >> 1) * 8]);
                asm volatile("ldmatrix.sync.aligned.m8n8.x4.shared.b16 {%0,%1,%2,%3}, [%4];\n"
                             : "=r"(a[mf][0]), "=r"(a[mf][1]), "=r"(a[mf][2]), "=r"(a[mf][3])
                             : "r"(ad));
            }
            unsigned b[8][2];
#pragma unroll
            for (int jp = 0; jp < 4; jp++) {
                unsigned bd = (unsigned)__cvta_generic_to_shared(
                    &Bt[wn + jp * 16 + (sub & 1) * 8 + rr][ks + (sub >> 1) * 8]);
                unsigned t0, t1, t2, t3;
                asm volatile("ldmatrix.sync.aligned.m8n8.x4.shared.b16 {%0,%1,%2,%3}, [%4];\n"
                             : "=r"(t0), "=r"(t1), "=r"(t2), "=r"(t3)
                             : "r"(bd));
                b[2 * jp][0] = t0; b[2 * jp][1] = t2;
                b[2 * jp + 1][0] = t1; b[2 * jp + 1][1] = t3;
            }
#pragma unroll
            for (int mf = 0; mf < 2; mf++)
#pragma unroll
                for (int j = 0; j < 8; j++)
                    asm volatile(
                        "mma.sync.aligned.m16n8k16.row.col.f32.bf16.bf16.f32 "
                        "{%0,%1,%2,%3}, {%4,%5,%6,%7}, {%8,%9}, {%0,%1,%2,%3};\n"
                        : "+f"(acc[mf][j][0]), "+f"(acc[mf][j][1]),
                          "+f"(acc[mf][j][2]), "+f"(acc[mf][j][3])
                        : "r"(a[mf][0]), "r"(a[mf][1]), "r"(a[mf][2]), "r"(a[mf][3]),
                          "r"(b[j][0]), "r"(b[j][1]));
        }
        __syncthreads();
    }
    rs[t] = sq;
    __syncthreads();
    if (t < 128) invn[t] = 1.f / fmaxf(sqrtf(rs[2 * t] + rs[2 * t + 1]), F_EPS);
    __syncthreads();
    int gid = lane >> 2, tig = lane & 3;
#pragma unroll
    for (int mf = 0; mf < 2; mf++)
#pragma unroll
        for (int j = 0; j < 8; j++)
#pragma unroll
            for (int e = 0; e < 4; e++) {
                int rl = wm + mf * 16 + gid + ((e >> 1) ? 8 : 0);
                int cl = wn + j * 8 + 2 * tig + (e & 1);
                int c = ny * 128 + cl;
                if (c < NC) {
                    float s = acc[mf][j][e] * invn[rl];
                    float dist = sqrtf(fmaxf(1.f + g_cn2[c] - 2.f * s, 0.f));
                    float h = F_MARGIN - dist;
                    if (h > 0.f) atomicAdd(&g_pair[lab[rl] * NCP + c], h);
                }
            }
}

// ---------------- final reductions: topo + margin + combine ----------------
__device__ __forceinline__ float blk_sum(float v, float* red) {
    for (int o = 16; o; o >>= 1) v += __shfl_xor_sync(0xffffffffu, v, o);
    int t = threadIdx.x;
    __syncthreads();
    if ((t & 31) == 0) red[t >> 5] = v;
    __syncthreads();
    float s = 0.f;
#pragma unroll
    for (int i = 0; i < 8; i++) s += red[i];
    return s;
}

__global__ void k_final(const float* __restrict__ M, float* __restrict__ out) {
    __shared__ float red[8];
    int t = threadIdx.x;
    float pmax = __uint_as_float(g_pmax);
    float minv = 1.f / __uint_as_float(g_mmax);
    float pr = (t < NC && g_counts[t] > 0) ? 1.f : 0.f;
    float npres = blk_sum(pr, red);
    bool gate = npres >= 2.f;
    // topo
    float ts = 0.f, nup = 0.f;
    for (int idx = t; idx < NC * NC; idx += 256) {
        int i = idx / NC, j = idx % NC;
        if (j > i && g_counts[i] > 0 && g_counts[j] > 0) {
            float cd = g_pdist[idx] / pmax;
            float tp = M[idx] * minv;
            float d = cd - tp;
            ts += d * d; nup += 1.f;
        }
    }
    ts = blk_sum(ts, red);
    nup = blk_sum(nup, red);
    float loss_topo = gate ? ts / fmaxf(nup, 1.f) : 0.f;
    // margin
    float ms = 0.f, np = 0.f;
    for (int idx = t; idx < NC * NC; idx += 256) {
        int i = idx / NC, j = idx % NC;
        if (i != j && g_counts[i] > 0 && g_counts[j] > 0 && M[idx] * minv < F_TOPO_TH) {
            ms += g_pair[i * NCP + j] / fmaxf((float)g_counts[i], 1.f);
            np += 1.f;
        }
    }
    ms = blk_sum(ms, red);
    np = blk_sum(np, red);
    float loss_margin = (gate && np > 0.f) ? ms / fmaxf(np, 1.f) : 0.f;
    if (t == 0) {
        float ce = g_ce / (float)BATCH;
        out[0] = ce + 0.1f * loss_topo + 0.05f * loss_margin;
        out[1] = ce;
        out[2] = loss_topo;
        out[3] = loss_margin;
    }
}

// ---------------- launch ----------------
extern "C" void kernel_launch(void* const* d_in, const int* in_sizes, int n_in,
                              void* d_out, int out_size) {
    const float* logits = nullptr;
    const int*   labels = nullptr;
    const float* emb    = nullptr;
    const float* M      = nullptr;
    for (int i = 0; i < n_in; i++) {
        if (in_sizes[i] == BATCH * NC)      logits = (const float*)d_in[i];
        else if (in_sizes[i] == BATCH)      labels = (const int*)d_in[i];
        else if (in_sizes[i] == BATCH * DIM) emb   = (const float*)d_in[i];
        else if (in_sizes[i] == NC * NC)    M      = (const float*)d_in[i];
    }
    float* out = (float*)d_out;

    cudaFuncSetAttribute(k_segsum, cudaFuncAttributeMaxDynamicSharedMemorySize,
                         8 * NC * 16 * (int)sizeof(float));

    k_init<<<64, 256>>>();
    k_ce<<<BATCH / 8, 256>>>(logits, labels);
    k_mmax<<<32, 256>>>(M);
    k_segsum<<<DIM / 16, 256, 8 * NC * 16 * sizeof(float)>>>(emb, labels);
    k_centfin<<<NCP, 256>>>();
    k_pdist<<<NC, 256>>>();
    k_margin<<<dim3(BATCH / 128, 2), 256>>>(emb, labels);
    k_final<<<1, 256>>>(M, out);
}

// round 9
// speedup vs baseline: 4.4621x; 4.4621x over previous
#include <cuda_runtime.h>
#include <cuda_bf16.h>
#include <math.h>

#define BATCH 16384
#define DIM   2048
#define NC    250
#define NCP   256
#define NCHUNK 64
#define F_MARGIN 1.2f
#define F_TOPO_TH 0.3f
#define F_EPS 1e-12f

// ---------------- scratch (static device memory; no allocs) ----------------
__device__ __align__(16) float          g_cent[NC * DIM];
__device__ __align__(16) __nv_bfloat16  g_cbf[NCP * DIM];
__device__ float        g_cn2[NCP];
__device__ float        g_c2[NC];
__device__ int          g_counts[NCP];
__device__ int          g_off[NCP];
__device__ int          g_order[BATCH];
__device__ int          g_chist[NCHUNK * NCP];
__device__ int          g_choff[NCHUNK * NCP];
__device__ float        g_pair[NC * NCP];
__device__ float        g_pdist[NC * NC];
__device__ float        g_acc[4];
__device__ float        g_ce;
__device__ unsigned int g_pmax;
__device__ unsigned int g_mmax;

__device__ __forceinline__ unsigned sptr(const void* p) {
    return (unsigned)__cvta_generic_to_shared(p);
}
#define CP_ASYNC16(dst, src) asm volatile("cp.async.cg.shared.global [%0], [%1], 16;\n" ::"r"(dst), "l"(src))
#define CP_COMMIT()  asm volatile("cp.async.commit_group;\n" ::: "memory")
#define CP_WAIT0()   asm volatile("cp.async.wait_group 0;\n" ::: "memory")

__device__ __forceinline__ float blk_sum(float v, float* red) {
    for (int o = 16; o; o >>= 1) v += __shfl_xor_sync(0xffffffffu, v, o);
    int t = threadIdx.x;
    __syncthreads();
    if ((t & 31) == 0) red[t >> 5] = v;
    __syncthreads();
    float s = 0.f;
#pragma unroll
    for (int i = 0; i < 8; i++) s += red[i];
    return s;
}

// ---------------- init ----------------
__global__ void k_init() {
    int i = blockIdx.x * blockDim.x + threadIdx.x;
    int stride = gridDim.x * blockDim.x;
    for (int k = i; k < NC * NCP; k += stride) g_pair[k] = 0.f;
    for (int k = NC * DIM + i; k < NCP * DIM; k += stride) g_cbf[k] = __float2bfloat16(0.f);
    if (i < NCP - NC) g_cn2[NC + i] = 0.f;
    if (i < 4) g_acc[i] = 0.f;
    if (i == 0) { g_ce = 0.f; g_pmax = 0u; g_mmax = 0u; }
}

// ---------------- cross-entropy (1 warp / row) ----------------
__global__ void k_ce(const float* __restrict__ logits, const int* __restrict__ labels) {
    __shared__ float bsum;
    if (threadIdx.x == 0) bsum = 0.f;
    __syncthreads();
    int w = threadIdx.x >> 5, lane = threadIdx.x & 31;
    int row = blockIdx.x * 8 + w;
    const float* lr = logits + (size_t)row * NC;
    float x[8], m = -1e30f;
#pragma unroll
    for (int i = 0; i < 8; i++) {
        int c = lane + 32 * i;
        x[i] = (c < NC) ? lr[c] : -1e30f;
        m = fmaxf(m, x[i]);
    }
    for (int o = 16; o; o >>= 1) m = fmaxf(m, __shfl_xor_sync(0xffffffffu, m, o));
    float s = 0.f;
#pragma unroll
    for (int i = 0; i < 8; i++) { int c = lane + 32 * i; if (c < NC) s += expf(x[i] - m); }
    for (int o = 16; o; o >>= 1) s += __shfl_xor_sync(0xffffffffu, s, o);
    if (lane == 0) {
        int lab = labels[row];
        atomicAdd(&bsum, -((lr[lab] - m) - logf(s)));
    }
    __syncthreads();
    if (threadIdx.x == 0) atomicAdd(&g_ce, bsum);
}

// ---------------- max of topo matrix ----------------
__global__ void k_mmax(const float* __restrict__ M) {
    __shared__ float wm[8];
    float m = 0.f;
    for (int i = blockIdx.x * blockDim.x + threadIdx.x; i < NC * NC; i += gridDim.x * blockDim.x)
        m = fmaxf(m, M[i]);
    for (int o = 16; o; o >>= 1) m = fmaxf(m, __shfl_xor_sync(0xffffffffu, m, o));
    if ((threadIdx.x & 31) == 0) wm[threadIdx.x >> 5] = m;
    __syncthreads();
    if (threadIdx.x == 0) {
        float r = 0.f;
#pragma unroll
        for (int i = 0; i < 8; i++) r = fmaxf(r, wm[i]);
        atomicMax(&g_mmax, __float_as_uint(r));
    }
}

// ---------------- label sort: per-chunk histogram (int atomics: deterministic) ----------------
__global__ void k_chist(const int* __restrict__ labels) {
    __shared__ int h[NCP];
    int t = threadIdx.x;
    h[t] = 0;
    __syncthreads();
    atomicAdd(&h[labels[blockIdx.x * 256 + t]], 1);
    __syncthreads();
    g_chist[blockIdx.x * NCP + t] = h[t];
}

// ---------------- class totals + exclusive scan + per-chunk bases ----------------
__global__ void k_offsets() {
    __shared__ int s[NCP];
    int c = threadIdx.x;
    int tot = 0;
    for (int ch = 0; ch < NCHUNK; ch++) tot += g_chist[ch * NCP + c];
    s[c] = tot;
    __syncthreads();
    for (int d = 1; d < NCP; d <<= 1) {
        int v = (c >= d) ? s[c - d] : 0;
        __syncthreads();
        s[c] += v;
        __syncthreads();
    }
    int base = s[c] - tot;
    g_off[c] = base;
    g_counts[c] = tot;
    int run = base;
    for (int ch = 0; ch < NCHUNK; ch++) {
        g_choff[ch * NCP + c] = run;
        run += g_chist[ch * NCP + c];
    }
}

// ---------------- stable permutation: rank within chunk ----------------
__global__ void k_perm(const int* __restrict__ labels) {
    __shared__ int sl[256];
    int t = threadIdx.x;
    int row = blockIdx.x * 256 + t;
    int myl = labels[row];
    sl[t] = myl;
    __syncthreads();
    int rank = 0;
    for (int r2 = 0; r2 < t; r2++) rank += (sl[r2] == myl) ? 1 : 0;
    g_order[g_choff[blockIdx.x * NCP + myl] + rank] = row;
}

// ---------------- centroid gather: 1 block/class, register accumulators ----------------
__global__ __launch_bounds__(256) void k_centroid(const float* __restrict__ emb) {
    __shared__ int so[256];
    __shared__ float red[8];
    int c = blockIdx.x, t = threadIdx.x;
    int cnt = g_counts[c], off = g_off[c];
    float a[8];
#pragma unroll
    for (int k = 0; k < 8; k++) a[k] = 0.f;
    for (int base = 0; base < cnt; base += 256) {
        int nb = min(256, cnt - base);
        __syncthreads();
        if (t < nb) so[t] = g_order[off + base + t];
        __syncthreads();
        for (int i = 0; i < nb; i++) {
            const float* r = emb + (size_t)so[i] * DIM;
            float4 x = *(const float4*)(r + t * 4);
            float4 y = *(const float4*)(r + 1024 + t * 4);
            a[0] += x.x; a[1] += x.y; a[2] += x.z; a[3] += x.w;
            a[4] += y.x; a[5] += y.y; a[6] += y.z; a[7] += y.w;
        }
    }
    float denom = 1.f / fmaxf((float)cnt, 1.f);
    float v[8], sq = 0.f;
#pragma unroll
    for (int k = 0; k < 8; k++) { v[k] = a[k] * denom; sq += v[k] * v[k]; }
    *(float4*)(g_cent + (size_t)c * DIM + t * 4) = make_float4(v[0], v[1], v[2], v[3]);
    *(float4*)(g_cent + (size_t)c * DIM + 1024 + t * 4) = make_float4(v[4], v[5], v[6], v[7]);
    float tot = blk_sum(sq, red);
    float inv = 1.f / fmaxf(sqrtf(tot), F_EPS);
    union { __nv_bfloat16 h[4]; uint2 u; } p0, p1;
    float q = 0.f;
#pragma unroll
    for (int k = 0; k < 4; k++) {
        p0.h[k] = __float2bfloat16(v[k] * inv);
        p1.h[k] = __float2bfloat16(v[4 + k] * inv);
        float f0 = __bfloat162float(p0.h[k]), f1 = __bfloat162float(p1.h[k]);
        q += f0 * f0 + f1 * f1;
    }
    *(uint2*)(g_cbf + (size_t)c * DIM + t * 4) = p0.u;
    *(uint2*)(g_cbf + (size_t)c * DIM + 1024 + t * 4) = p1.u;
    float tq = blk_sum(q, red);
    if (t == 0) { g_cn2[c] = tq; g_c2[c] = tot; }
}

// ---------------- pdist: tiled fp32 GEMM, grid 8x8, no atomics ----------------
__global__ void k_pdist() {
    __shared__ float As[32][68];
    __shared__ float Bs[32][68];
    __shared__ float wm[8];
    int tx = threadIdx.x, ty = threadIdx.y;
    int tid = ty * 16 + tx;
    int by = blockIdx.y, bx = blockIdx.x;
    float a00 = 0.f, a01 = 0.f, a10 = 0.f, a11 = 0.f;
    int lrow = tid >> 3, lq = tid & 7;
    int gr = by * 32 + lrow, gc = bx * 32 + lrow;
    for (int kc = 0; kc < DIM; kc += 64) {
        float4 z = make_float4(0, 0, 0, 0);
        float4 v0 = (gr < NC) ? *(const float4*)(g_cent + (size_t)gr * DIM + kc + lq * 8) : z;
        float4 v1 = (gr < NC) ? *(const float4*)(g_cent + (size_t)gr * DIM + kc + lq * 8 + 4) : z;
        float4 w0 = (gc < NC) ? *(const float4*)(g_cent + (size_t)gc * DIM + kc + lq * 8) : z;
        float4 w1 = (gc < NC) ? *(const float4*)(g_cent + (size_t)gc * DIM + kc + lq * 8 + 4) : z;
        *(float4*)&As[lrow][lq * 8] = v0; *(float4*)&As[lrow][lq * 8 + 4] = v1;
        *(float4*)&Bs[lrow][lq * 8] = w0; *(float4*)&Bs[lrow][lq * 8 + 4] = w1;
        __syncthreads();
#pragma unroll
        for (int kg = 0; kg < 16; kg++) {
            float4 r0 = *(float4*)&As[ty * 2][kg * 4];
            float4 r1 = *(float4*)&As[ty * 2 + 1][kg * 4];
            float4 c0 = *(float4*)&Bs[tx * 2][kg * 4];
            float4 c1 = *(float4*)&Bs[tx * 2 + 1][kg * 4];
            a00 += r0.x * c0.x + r0.y * c0.y + r0.z * c0.z + r0.w * c0.w;
            a01 += r0.x * c1.x + r0.y * c1.y + r0.z * c1.z + r0.w * c1.w;
            a10 += r1.x * c0.x + r1.y * c0.y + r1.z * c0.z + r1.w * c0.w;
            a11 += r1.x * c1.x + r1.y * c1.y + r1.z * c1.z + r1.w * c1.w;
        }
        __syncthreads();
    }
    int i0 = by * 32 + ty * 2, j0 = bx * 32 + tx * 2;
    float pm = 0.f;
    float dots[4] = {a00, a01, a10, a11};
#pragma unroll
    for (int e = 0; e < 4; e++) {
        int i = i0 + (e >> 1), j = j0 + (e & 1);
        if (i < NC && j < NC) {
            float pd = sqrtf(fmaxf(g_c2[i] + g_c2[j] - 2.f * dots[e], 0.f) + F_EPS);
            g_pdist[i * NC + j] = pd;
            if (g_counts[i] > 0 && g_counts[j] > 0) pm = fmaxf(pm, pd);
        }
    }
    for (int o = 16; o; o >>= 1) pm = fmaxf(pm, __shfl_xor_sync(0xffffffffu, pm, o));
    if ((tid & 31) == 0) wm[tid >> 5] = pm;
    __syncthreads();
    if (tid == 0) {
        float r = 0.f;
#pragma unroll
        for (int k = 0; k < 8; k++) r = fmaxf(r, wm[k]);
        atomicMax(&g_pmax, __float_as_uint(r));
    }
}

// ---------------- margin GEMM: 128m x 256n tile, K=32 chunks, double-buffered ----------------
__global__ __launch_bounds__(512, 1) void k_margin(const float* __restrict__ emb,
                                                   const int* __restrict__ labels) {
    extern __shared__ char smx[];
    __nv_bfloat16 (*At)[128][40] = (__nv_bfloat16(*)[128][40])smx;            // 20480 B
    __nv_bfloat16 (*Bt)[256][40] = (__nv_bfloat16(*)[256][40])(smx + 20480);  // 40960 B
    int*   lab  = (int*)(smx + 61440);
    float* invn = (float*)(smx + 61952);
    float* cn2s = (float*)(smx + 62464);
    int t = threadIdx.x, bx = blockIdx.x;
    if (t < 128) lab[t] = labels[bx * 128 + t];
    if (t < 256) cn2s[t] = g_cn2[t];
    int arow = t >> 2, aq = t & 3;                 // A: 128 rows x 32 cols, 4 thr/row
    int brow = t >> 1, bq = t & 1;                 // B: 256 rows x 32 cols, 2 thr/row
    const float* abase = emb + (size_t)(bx * 128 + arow) * DIM + aq * 8;
    const __nv_bfloat16* bbase = g_cbf + (size_t)brow * DIM + bq * 16;
    float sq = 0.f;
    // prologue: chunk 0
    {
        float4 c0 = *(const float4*)abase;
        float4 c1 = *(const float4*)(abase + 4);
        sq += c0.x * c0.x + c0.y * c0.y + c0.z * c0.z + c0.w * c0.w
            + c1.x * c1.x + c1.y * c1.y + c1.z * c1.z + c1.w * c1.w;
        union { __nv_bfloat16 h[8]; uint4 u; } pk;
        pk.h[0] = __float2bfloat16(c0.x); pk.h[1] = __float2bfloat16(c0.y);
        pk.h[2] = __float2bfloat16(c0.z); pk.h[3] = __float2bfloat16(c0.w);
        pk.h[4] = __float2bfloat16(c1.x); pk.h[5] = __float2bfloat16(c1.y);
        pk.h[6] = __float2bfloat16(c1.z); pk.h[7] = __float2bfloat16(c1.w);
        *(uint4*)&At[0][arow][aq * 8] = pk.u;
        CP_ASYNC16(sptr(&Bt[0][brow][bq * 16]), bbase);
        CP_ASYNC16(sptr(&Bt[0][brow][bq * 16 + 8]), bbase + 8);
        CP_COMMIT();
    }
    int wid = t >> 5, lane = t & 31;
    int wmr = (wid & 3) * 32, wnc = (wid >> 2) * 64;
    int sub = lane >> 3, rr = lane & 7;
    float acc[2][8][4];
#pragma unroll
    for (int a = 0; a < 2; a++)
#pragma unroll
        for (int b = 0; b < 8; b++)
#pragma unroll
            for (int e = 0; e < 4; e++) acc[a][b][e] = 0.f;

    for (int i = 0; i < 64; i++) {
        int p = i & 1;
        CP_WAIT0();
        __syncthreads();
        float4 n0, n1;
        if (i < 63) {
            const float* ap = abase + (i + 1) * 32;
            n0 = *(const float4*)ap;
            n1 = *(const float4*)(ap + 4);
            const __nv_bfloat16* bp = bbase + (i + 1) * 32;
            CP_ASYNC16(sptr(&Bt[p ^ 1][brow][bq * 16]), bp);
            CP_ASYNC16(sptr(&Bt[p ^ 1][brow][bq * 16 + 8]), bp + 8);
            CP_COMMIT();
        }
#pragma unroll
        for (int ks = 0; ks < 32; ks += 16) {
            unsigned af[2][4];
#pragma unroll
            for (int mf = 0; mf < 2; mf++) {
                unsigned ad = sptr(&At[p][wmr + mf * 16 + (sub & 1) * 8 + rr][ks + (sub >> 1) * 8]);
                asm volatile("ldmatrix.sync.aligned.m8n8.x4.shared.b16 {%0,%1,%2,%3}, [%4];\n"
                             : "=r"(af[mf][0]), "=r"(af[mf][1]), "=r"(af[mf][2]), "=r"(af[mf][3])
                             : "r"(ad));
            }
            unsigned bf[8][2];
#pragma unroll
            for (int jp = 0; jp < 4; jp++) {
                unsigned bd = sptr(&Bt[p][wnc + jp * 16 + (sub & 1) * 8 + rr][ks + (sub >> 1) * 8]);
                unsigned t0, t1, t2, t3;
                asm volatile("ldmatrix.sync.aligned.m8n8.x4.shared.b16 {%0,%1,%2,%3}, [%4];\n"
                             : "=r"(t0), "=r"(t1), "=r"(t2), "=r"(t3)
                             : "r"(bd));
                bf[2 * jp][0] = t0; bf[2 * jp][1] = t2;
                bf[2 * jp + 1][0] = t1; bf[2 * jp + 1][1] = t3;
            }
#pragma unroll
            for (int mf = 0; mf < 2; mf++)
#pragma unroll
                for (int j = 0; j < 8; j++)
                    asm volatile(
                        "mma.sync.aligned.m16n8k16.row.col.f32.bf16.bf16.f32 "
                        "{%0,%1,%2,%3}, {%4,%5,%6,%7}, {%8,%9}, {%0,%1,%2,%3};\n"
                        : "+f"(acc[mf][j][0]), "+f"(acc[mf][j][1]),
                          "+f"(acc[mf][j][2]), "+f"(acc[mf][j][3])
                        : "r"(af[mf][0]), "r"(af[mf][1]), "r"(af[mf][2]), "r"(af[mf][3]),
                          "r"(bf[j][0]), "r"(bf[j][1]));
        }
        if (i < 63) {
            sq += n0.x * n0.x + n0.y * n0.y + n0.z * n0.z + n0.w * n0.w
                + n1.x * n1.x + n1.y * n1.y + n1.z * n1.z + n1.w * n1.w;
            union { __nv_bfloat16 h[8]; uint4 u; } pk;
            pk.h[0] = __float2bfloat16(n0.x); pk.h[1] = __float2bfloat16(n0.y);
            pk.h[2] = __float2bfloat16(n0.z); pk.h[3] = __float2bfloat16(n0.w);
            pk.h[4] = __float2bfloat16(n1.x); pk.h[5] = __float2bfloat16(n1.y);
            pk.h[6] = __float2bfloat16(n1.z); pk.h[7] = __float2bfloat16(n1.w);
            *(uint4*)&At[p ^ 1][arow][aq * 8] = pk.u;
        }
    }
    // per-row inverse norms (4 consecutive threads share a row)
    sq += __shfl_xor_sync(0xffffffffu, sq, 1);
    sq += __shfl_xor_sync(0xffffffffu, sq, 2);
    if (aq == 0) invn[arow] = 1.f / fmaxf(sqrtf(sq), F_EPS);
    __syncthreads();
    int gid = lane >> 2, tig = lane & 3;
#pragma unroll
    for (int mf = 0; mf < 2; mf++)
#pragma unroll
        for (int j = 0; j < 8; j++)
#pragma unroll
            for (int e = 0; e < 4; e++) {
                int rl = wmr + mf * 16 + gid + ((e >> 1) ? 8 : 0);
                int cl = wnc + j * 8 + 2 * tig + (e & 1);
                if (cl < NC) {
                    float s = acc[mf][j][e] * invn[rl];
                    float dist = sqrtf(fmaxf(1.f + cn2s[cl] - 2.f * s, 0.f));
                    float h = F_MARGIN - dist;
                    if (h > 0.f) atomicAdd(&g_pair[lab[rl] * NCP + cl], h);
                }
            }
}

// ---------------- pair losses: 1 block per class-row ----------------
__global__ void k_pairloss(const float* __restrict__ M) {
    __shared__ float red[8];
    int i = blockIdx.x, t = threadIdx.x;
    float pmax = __uint_as_float(g_pmax);
    float minv = 1.f / __uint_as_float(g_mmax);
    bool pi = g_counts[i] > 0;
    float ts = 0.f, nup = 0.f, ms = 0.f, np = 0.f;
    if (t < NC && pi && g_counts[t] > 0) {
        int j = t;
        float tp = M[i * NC + j] * minv;
        if (j > i) {
            float d = g_pdist[i * NC + j] / pmax - tp;
            ts = d * d; nup = 1.f;
        }
        if (j != i && tp < F_TOPO_TH) {
            ms = g_pair[i * NCP + j] / fmaxf((float)g_counts[i], 1.f);
            np = 1.f;
        }
    }
    ts = blk_sum(ts, red);
    nup = blk_sum(nup, red);
    ms = blk_sum(ms, red);
    np = blk_sum(np, red);
    if (t == 0) {
        atomicAdd(&g_acc[0], ts);
        atomicAdd(&g_acc[1], nup);
        atomicAdd(&g_acc[2], ms);
        atomicAdd(&g_acc[3], np);
    }
}

// ---------------- combine ----------------
__global__ void k_combine(float* __restrict__ out) {
    __shared__ float red[8];
    int t = threadIdx.x;
    float pr = (t < NC && g_counts[t] > 0) ? 1.f : 0.f;
    float npres = blk_sum(pr, red);
    if (t == 0) {
        bool gate = npres >= 2.f;
        float lt = gate ? g_acc[0] / fmaxf(g_acc[1], 1.f) : 0.f;
        float np = g_acc[3];
        float lm = (gate && np > 0.f) ? g_acc[2] / fmaxf(np, 1.f) : 0.f;
        float ce = g_ce / (float)BATCH;
        out[0] = ce + 0.1f * lt + 0.05f * lm;
        out[1] = ce;
        out[2] = lt;
        out[3] = lm;
    }
}

// ---------------- launch ----------------
extern "C" void kernel_launch(void* const* d_in, const int* in_sizes, int n_in,
                              void* d_out, int out_size) {
    const float* logits = nullptr;
    const int*   labels = nullptr;
    const float* emb    = nullptr;
    const float* M      = nullptr;
    for (int i = 0; i < n_in; i++) {
        if (in_sizes[i] == BATCH * NC)       logits = (const float*)d_in[i];
        else if (in_sizes[i] == BATCH)       labels = (const int*)d_in[i];
        else if (in_sizes[i] == BATCH * DIM) emb    = (const float*)d_in[i];
        else if (in_sizes[i] == NC * NC)     M      = (const float*)d_in[i];
    }
    float* out = (float*)d_out;

    static int cfg_done = 0;
    if (!cfg_done) {
        cudaFuncSetAttribute(k_margin, cudaFuncAttributeMaxDynamicSharedMemorySize, 63488);
        cfg_done = 1;
    }

    k_init<<<64, 256>>>();
    k_ce<<<BATCH / 8, 256>>>(logits, labels);
    k_mmax<<<32, 256>>>(M);
    k_chist<<<NCHUNK, 256>>>(labels);
    k_offsets<<<1, NCP>>>();
    k_perm<<<NCHUNK, 256>>>(labels);
    k_centroid<<<NC, 256>>>(emb);
    k_pdist<<<dim3(8, 8), dim3(16, 16)>>>();
    k_margin<<<BATCH / 128, 512, 63488>>>(emb, labels);
    k_pairloss<<<NC, 256>>>(M);
    k_combine<<<1, 256>>>(out);
}